// round 5
// baseline (speedup 1.0000x reference)
#include <cuda_runtime.h>
#include <cstdint>

#define NN   8192
#define KF   256
#define KX   512
#define TOPC 32
#define EPSF 1e-10f

// ---------------- device scratch ----------------
__device__ float  g_X[(size_t)NN * KX];   // [n][0..255]=A_m*cos, [256..511]=A_m*sin
__device__ float  g_sq[NN];
__device__ float  g_d[NN];                // rowsum + eps (fp32, XLA-order)
__device__ double g_rowPS[NN];
__device__ int    g_rowPC[NN];
__device__ float  g_tau;

// ---------------- packed fp32x2 helpers (Blackwell FFMA2) ----------------
__device__ __forceinline__ unsigned long long dup2(float v) {
    unsigned long long r;
    asm("mov.b64 %0, {%1, %1};" : "=l"(r) : "f"(v));
    return r;
}
__device__ __forceinline__ void ffma2(unsigned long long& acc,
                                      unsigned long long a, unsigned long long b) {
    asm("fma.rn.f32x2 %0, %1, %2, %0;" : "+l"(acc) : "l"(a), "l"(b));
}
__device__ __forceinline__ float2 unpack2(unsigned long long v) {
    float lo, hi;
    asm("mov.b64 {%0, %1}, %2;" : "=f"(lo), "=f"(hi) : "l"(v));
    return make_float2(lo, hi);
}

// =====================================================================
// Stage A: top-32 mask, features, sq. One warp per row.
// =====================================================================
__global__ void prep_kernel(const float* __restrict__ P, const float* __restrict__ A) {
    int warp = threadIdx.x >> 5, lane = threadIdx.x & 31;
    int n = blockIdx.x * 4 + warp;
    if (n >= NN) return;
    const float* Arow = A + (size_t)n * KF;
    const float* Prow = P + (size_t)n * KF;

    float a[8], tmp[8];
#pragma unroll
    for (int j = 0; j < 8; j++) { a[j] = Arow[j * 32 + lane]; tmp[j] = a[j]; }

    unsigned sel = 0u;
    for (int it = 0; it < TOPC; it++) {
        float lm = -1e30f; int jb = 0;
#pragma unroll
        for (int j = 0; j < 8; j++) if (tmp[j] > lm) { lm = tmp[j]; jb = j; }
        float M = lm;
#pragma unroll
        for (int o = 16; o; o >>= 1) M = fmaxf(M, __shfl_xor_sync(0xffffffffu, M, o));
        unsigned ball = __ballot_sync(0xffffffffu, lm == M);
        int src = __ffs(ball) - 1;
        if (lane == src) { tmp[jb] = -1e30f; sel |= 1u << jb; }
    }

    float sq = 0.f;
#pragma unroll
    for (int j = 0; j < 8; j++) {
        int k = j * 32 + lane;
        float am = (sel >> j & 1u) ? a[j] : 0.f;
        sq = __fmaf_rn(am, am, sq);
        float p = Prow[k];
        float cc = cosf(p);
        float ss = sinf(p);
        g_X[(size_t)n * KX + k]      = __fmul_rn(am, cc);
        g_X[(size_t)n * KX + KF + k] = __fmul_rn(am, ss);
    }
#pragma unroll
    for (int o = 16; o; o >>= 1) sq = __fadd_rn(sq, __shfl_xor_sync(0xffffffffu, sq, o));
    if (lane == 0) g_sq[n] = sq;
}

// =====================================================================
// Stage B: R tile GEMM, fp32 sequential-k FMA via packed fma.rn.f32x2
// (bitwise identical per-element rounding to scalar __fmaf_rn chain).
// 128x128 tiles, 256 threads, 8x8 micro-tile. Triangular + mirror.
// =====================================================================
#define TS 128
#define KT 16

__global__ void __launch_bounds__(256) sgemm_kernel(float* __restrict__ out) {
    int bi = blockIdx.y, bj = blockIdx.x;
    if (bj > bi) return;
    int bm = bi * TS, bn = bj * TS;
    int tid = threadIdx.x;
    int tx = tid & 15, ty = tid >> 4;

    __shared__ float sA[KT][TS + 4];   // [k][m]
    __shared__ float sB[KT][TS + 4];

    float4 pa[2], pb[2];

#define LDG_TILE(KTI)                                                          \
    {                                                                          \
        _Pragma("unroll")                                                      \
        for (int i = 0; i < 2; i++) {                                          \
            int f = tid + i * 256;                                             \
            int row = f >> 2, kq = f & 3;                                      \
            pa[i] = *(const float4*)&g_X[(size_t)(bm + row) * KX + (KTI) * KT + kq * 4]; \
            pb[i] = *(const float4*)&g_X[(size_t)(bn + row) * KX + (KTI) * KT + kq * 4]; \
        }                                                                      \
    }

#define STS_TILE()                                                             \
    {                                                                          \
        _Pragma("unroll")                                                      \
        for (int i = 0; i < 2; i++) {                                          \
            int f = tid + i * 256;                                             \
            int row = f >> 2, kq = f & 3;                                      \
            sA[kq * 4 + 0][row] = pa[i].x; sA[kq * 4 + 1][row] = pa[i].y;      \
            sA[kq * 4 + 2][row] = pa[i].z; sA[kq * 4 + 3][row] = pa[i].w;      \
            sB[kq * 4 + 0][row] = pb[i].x; sB[kq * 4 + 1][row] = pb[i].y;      \
            sB[kq * 4 + 2][row] = pb[i].z; sB[kq * 4 + 3][row] = pb[i].w;      \
        }                                                                      \
    }

    // packed compute: acc2[r][c2] holds columns (tx*8+2*c2, tx*8+2*c2+1)
#define COMPUTE_TILE(ACC)                                                      \
    {                                                                          \
        _Pragma("unroll")                                                      \
        for (int kk = 0; kk < KT; kk++) {                                      \
            float4 a0 = *(const float4*)&sA[kk][ty * 8];                       \
            float4 a1 = *(const float4*)&sA[kk][ty * 8 + 4];                   \
            ulonglong2 bq0 = *(const ulonglong2*)&sB[kk][tx * 8];              \
            ulonglong2 bq1 = *(const ulonglong2*)&sB[kk][tx * 8 + 4];          \
            unsigned long long bp[4] = {bq0.x, bq0.y, bq1.x, bq1.y};           \
            float av[8] = {a0.x, a0.y, a0.z, a0.w, a1.x, a1.y, a1.z, a1.w};    \
            unsigned long long ap[8];                                          \
            _Pragma("unroll")                                                  \
            for (int r = 0; r < 8; r++) ap[r] = dup2(av[r]);                   \
            _Pragma("unroll")                                                  \
            for (int r = 0; r < 8; r++)                                        \
                _Pragma("unroll")                                              \
                for (int c2 = 0; c2 < 4; c2++)                                 \
                    ffma2(ACC[r][c2], ap[r], bp[c2]);                          \
        }                                                                      \
    }

    unsigned long long accC[8][4], accS[8][4];
#pragma unroll
    for (int r = 0; r < 8; r++)
#pragma unroll
        for (int c2 = 0; c2 < 4; c2++) { accC[r][c2] = 0ull; accS[r][c2] = 0ull; }

    LDG_TILE(0);
    for (int kt = 0; kt < 16; kt++) {          // cos features, k ascending
        __syncthreads();
        STS_TILE();
        __syncthreads();
        LDG_TILE(kt + 1);
        COMPUTE_TILE(accC);
    }
    for (int kt = 16; kt < 32; kt++) {         // sin features, k ascending
        __syncthreads();
        STS_TILE();
        __syncthreads();
        if (kt + 1 < 32) LDG_TILE(kt + 1);
        COMPUTE_TILE(accS);
    }

    // -------- epilogue: R = (accC+accS)/sqrt(sq_i*sq_j+eps), mirror --------
    float sqi[8], sqj[8];
#pragma unroll
    for (int r = 0; r < 8; r++) sqi[r] = g_sq[bm + ty * 8 + r];
#pragma unroll
    for (int c = 0; c < 8; c++) sqj[c] = g_sq[bn + tx * 8 + c];

    float v[8][8];
#pragma unroll
    for (int r = 0; r < 8; r++)
#pragma unroll
        for (int c2 = 0; c2 < 4; c2++) {
            float2 cc = unpack2(accC[r][c2]);
            float2 ss = unpack2(accS[r][c2]);
            float n0 = __fadd_rn(cc.x, ss.x);
            float n1 = __fadd_rn(cc.y, ss.y);
            float d0 = __fsqrt_rn(__fadd_rn(__fmul_rn(sqi[r], sqj[c2 * 2]), EPSF));
            float d1 = __fsqrt_rn(__fadd_rn(__fmul_rn(sqi[r], sqj[c2 * 2 + 1]), EPSF));
            v[r][c2 * 2]     = __fdiv_rn(n0, d0);
            v[r][c2 * 2 + 1] = __fdiv_rn(n1, d1);
        }

#pragma unroll
    for (int r = 0; r < 8; r++) {
        size_t o = (size_t)(bm + ty * 8 + r) * NN + bn + tx * 8;
        *(float4*)&out[o]     = make_float4(v[r][0], v[r][1], v[r][2], v[r][3]);
        *(float4*)&out[o + 4] = make_float4(v[r][4], v[r][5], v[r][6], v[r][7]);
    }
    if (bi != bj) {
#pragma unroll
        for (int c = 0; c < 8; c++) {
            size_t o = (size_t)(bn + tx * 8 + c) * NN + bm + ty * 8;
            *(float4*)&out[o]     = make_float4(v[0][c], v[1][c], v[2][c], v[3][c]);
            *(float4*)&out[o + 4] = make_float4(v[4][c], v[5][c], v[6][c], v[7][c]);
        }
    }
}

// =====================================================================
// Stage C (fused): rowsum in fp32 (XLA:GPU reduction order) + positive
// stats of R' = R/d from register-held values.
// =====================================================================
__global__ void __launch_bounds__(1024) rowsum_kernel(const float* __restrict__ R) {
    int row = blockIdx.x;
    const float* r = R + (size_t)row * NN;
    int t = threadIdx.x;

    float vals[8];
    float a0 = 0.f, a1 = 0.f;
#pragma unroll
    for (int j = 0; j < 4; j++) {
        int i = t * 2 + j * 2048;
        vals[j * 2]     = r[i];
        vals[j * 2 + 1] = r[i + 1];
        a0 = __fadd_rn(a0, vals[j * 2]);
        a1 = __fadd_rn(a1, vals[j * 2 + 1]);
    }
    float acc = __fadd_rn(a0, a1);
#pragma unroll
    for (int o = 16; o > 0; o >>= 1)
        acc = __fadd_rn(acc, __shfl_down_sync(0xffffffffu, acc, o));
    __shared__ float w[32];
    __shared__ float sd;
    if ((t & 31) == 0) w[t >> 5] = acc;
    __syncthreads();
    if (t < 32) {
        float vv = w[t];
#pragma unroll
        for (int o = 16; o > 0; o >>= 1)
            vv = __fadd_rn(vv, __shfl_down_sync(0xffffffffu, vv, o));
        if (t == 0) { float d = __fadd_rn(vv, EPSF); g_d[row] = d; sd = d; }
    }
    __syncthreads();

    float d = sd;
    double ps = 0.0; int pc = 0;
#pragma unroll
    for (int j = 0; j < 8; j++) {
        float rp = __fdiv_rn(vals[j], d);
        if (rp > 0.f) { ps += (double)rp; pc++; }
    }
#pragma unroll
    for (int o = 16; o > 0; o >>= 1) {
        ps += __shfl_down_sync(0xffffffffu, ps, o);
        pc += __shfl_down_sync(0xffffffffu, pc, o);
    }
    __shared__ double wps[32];
    __shared__ int    wpc[32];
    if ((t & 31) == 0) { wps[t >> 5] = ps; wpc[t >> 5] = pc; }
    __syncthreads();
    if (t < 32) {
        double p2 = wps[t]; int c2 = wpc[t];
#pragma unroll
        for (int o = 16; o > 0; o >>= 1) {
            p2 += __shfl_down_sync(0xffffffffu, p2, o);
            c2 += __shfl_down_sync(0xffffffffu, c2, o);
        }
        if (t == 0) { g_rowPS[row] = p2; g_rowPC[row] = c2; }
    }
}

// =====================================================================
// Stage D: tau = mean of strictly-positive R'
// =====================================================================
__global__ void __launch_bounds__(1024) tau_kernel() {
    __shared__ double sps[1024]; __shared__ long long spc[1024];
    double ps = 0.0; long long pc = 0;
    for (int rw = threadIdx.x; rw < NN; rw += 1024) { ps += g_rowPS[rw]; pc += g_rowPC[rw]; }
    sps[threadIdx.x] = ps; spc[threadIdx.x] = pc;
    __syncthreads();
    for (int o = 512; o > 0; o >>= 1) {
        if (threadIdx.x < o) {
            sps[threadIdx.x] += sps[threadIdx.x + o];
            spc[threadIdx.x] += spc[threadIdx.x + o];
        }
        __syncthreads();
    }
    if (threadIdx.x == 0) {
        float psf = (float)sps[0];
        float cf  = fmaxf((float)spc[0], 1.0f);
        float mean = __fdiv_rn(psf, cf);
        g_tau = (mean > 0.f) ? mean : 1.0f;
    }
}

// =====================================================================
// Stage E: R_hat = where(R/d >= tau, R/d, 0)   (in-place)
// =====================================================================
__global__ void thresh_kernel(float* __restrict__ out) {
    float tau = g_tau;
    const size_t tot = (size_t)NN * NN / 4;
    for (size_t i = (size_t)blockIdx.x * blockDim.x + threadIdx.x; i < tot;
         i += (size_t)gridDim.x * blockDim.x) {
        int row = (int)(i >> 11);
        float d = g_d[row];
        float4 v = ((const float4*)out)[i];
        v.x = __fdiv_rn(v.x, d); v.y = __fdiv_rn(v.y, d);
        v.z = __fdiv_rn(v.z, d); v.w = __fdiv_rn(v.w, d);
        v.x = (v.x >= tau) ? v.x : 0.f;
        v.y = (v.y >= tau) ? v.y : 0.f;
        v.z = (v.z >= tau) ? v.z : 0.f;
        v.w = (v.w >= tau) ? v.w : 0.f;
        ((float4*)out)[i] = v;
    }
}

// =====================================================================
extern "C" void kernel_launch(void* const* d_in, const int* in_sizes, int n_in,
                              void* d_out, int out_size) {
    const float* P = (const float*)d_in[0];
    const float* A = (const float*)d_in[1];
    float* out = (float*)d_out;

    prep_kernel<<<NN / 4, 128>>>(P, A);
    sgemm_kernel<<<dim3(64, 64), 256>>>(out);
    rowsum_kernel<<<NN, 1024>>>(out);
    tau_kernel<<<1, 1024>>>();
    thresh_kernel<<<4096, 256>>>(out);
}

// round 8
// speedup vs baseline: 1.2244x; 1.2244x over previous
#include <cuda_runtime.h>
#include <cstdint>

#define NN   8192
#define KF   256
#define KX   512
#define TOPC 32
#define EPSF 1e-10f

// ---------------- device scratch ----------------
__device__ float  g_X[(size_t)NN * KX];        // dense: [n][0..255]=Ac, [256..511]=As
__device__ float2 g_cvsv[(size_t)NN * TOPC];   // compact (cos,sin) values, ascending k
__device__ unsigned char g_idx[(size_t)NN * TOPC]; // compact k indices, ascending
__device__ float  g_sq[NN];
__device__ float  g_d[NN];
__device__ double g_rowPS[NN];
__device__ int    g_rowPC[NN];
__device__ float  g_tau;

// =====================================================================
// Stage A: top-32 mask, dense features, compact (idx, cos, sin) lists
// in ascending-k order, sq. One warp per row.
// =====================================================================
__global__ void prep_kernel(const float* __restrict__ P, const float* __restrict__ A) {
    int warp = threadIdx.x >> 5, lane = threadIdx.x & 31;
    int n = blockIdx.x * 4 + warp;
    if (n >= NN) return;
    const float* Arow = A + (size_t)n * KF;
    const float* Prow = P + (size_t)n * KF;

    float a[8], tmp[8];
#pragma unroll
    for (int j = 0; j < 8; j++) { a[j] = Arow[j * 32 + lane]; tmp[j] = a[j]; }

    unsigned sel = 0u;
    for (int it = 0; it < TOPC; it++) {
        float lm = -1e30f; int jb = 0;
#pragma unroll
        for (int j = 0; j < 8; j++) if (tmp[j] > lm) { lm = tmp[j]; jb = j; }
        float M = lm;
#pragma unroll
        for (int o = 16; o; o >>= 1) M = fmaxf(M, __shfl_xor_sync(0xffffffffu, M, o));
        unsigned ball = __ballot_sync(0xffffffffu, lm == M);
        int src = __ffs(ball) - 1;
        if (lane == src) { tmp[jb] = -1e30f; sel |= 1u << jb; }
    }

    float vc[8], vs[8];
    float sq = 0.f;
#pragma unroll
    for (int j = 0; j < 8; j++) {
        int k = j * 32 + lane;
        float am = (sel >> j & 1u) ? a[j] : 0.f;
        sq = __fmaf_rn(am, am, sq);
        float p = Prow[k];
        float cc = cosf(p);
        float ss = sinf(p);
        vc[j] = __fmul_rn(am, cc);
        vs[j] = __fmul_rn(am, ss);
        g_X[(size_t)n * KX + k]      = vc[j];
        g_X[(size_t)n * KX + KF + k] = vs[j];
    }
#pragma unroll
    for (int o = 16; o; o >>= 1) sq = __fadd_rn(sq, __shfl_xor_sync(0xffffffffu, sq, o));
    if (lane == 0) g_sq[n] = sq;

    // compact lists, ascending k (j-major then lane = ascending)
    int base = 0;
#pragma unroll
    for (int j = 0; j < 8; j++) {
        unsigned bit = (sel >> j) & 1u;
        unsigned ball = __ballot_sync(0xffffffffu, bit);
        if (bit) {
            int pos = base + __popc(ball & ((1u << lane) - 1u));
            g_idx[(size_t)n * TOPC + pos]  = (unsigned char)(j * 32 + lane);
            g_cvsv[(size_t)n * TOPC + pos] = make_float2(vc[j], vs[j]);
        }
        base += __popc(ball);
    }
}

// =====================================================================
// Stage B: sparse-aware GEMM, bit-identical to dense sequential-k fp32
// FMA chain (zero products skipped exactly).
// Block: 128n x 128m (two 64m subtiles), 512 threads.
// Warp = 1 n x 64 m; per j: uniform k, conflict-free LDS.128 gather from
// transposed tile T[k][m]=(cos,sin). Triangular grid + smem-staged mirror.
// =====================================================================
// smem byte offsets
#define SM_SCV   0                         // float2 [128][32]   32768
#define SM_SIDX  32768                     // u8     [128][32]    4096
#define SM_SQN   36864                     // float  [128]         512
#define SM_SQM   37376                     // float  [64]          256
#define SM_T     37632                     // float  [256][132] 135168
#define SM_VT    172800                    // float  [64][132]   33792
#define SM_TOTAL 206592

__global__ void __launch_bounds__(512) sgemm_sparse(float* __restrict__ out) {
    int bi = blockIdx.y, bj = blockIdx.x;
    if (bj > bi) return;
    int n0 = bi * 128, m0base = bj * 128;

    extern __shared__ char sm[];
    float2*        scv  = (float2*)(sm + SM_SCV);
    unsigned char* sidx = (unsigned char*)(sm + SM_SIDX);
    float*         sqn  = (float*)(sm + SM_SQN);
    float*         sqm  = (float*)(sm + SM_SQM);
    float*         T    = (float*)(sm + SM_T);
    float*         vT   = (float*)(sm + SM_VT);

    int tid = threadIdx.x;
    int w = tid >> 5, ln = tid & 31;

    // load n-side compact data (contiguous)
    {
        const float4* src = (const float4*)&g_cvsv[(size_t)n0 * TOPC];
        float4* dst = (float4*)scv;
        for (int i = tid; i < 4096; i += 512) dst[i] = src[i];
        const unsigned* isrc = (const unsigned*)&g_idx[(size_t)n0 * TOPC];
        unsigned* idst = (unsigned*)sidx;
        for (int i = tid; i < 1024; i += 512) idst[i] = isrc[i];
        if (tid < 128) sqn[tid] = g_sq[n0 + tid];
    }

    for (int s = 0; s < 2; s++) {
        int m0 = m0base + s * 64;
        __syncthreads();   // scv ready (s=0) / prior vT flush done (s=1)

        // build transposed tile T[k][2m..2m+1] = (cos, sin) for 64 m-rows
        {
            int m = tid >> 3;             // 0..63
            int kc = (tid & 7) * 32;      // 0..224
            const float* xr = &g_X[(size_t)(m0 + m) * KX];
#pragma unroll
            for (int it = 0; it < 8; it++) {
                int k = kc + it * 4;
                float4 c4 = *(const float4*)&xr[k];
                float4 s4 = *(const float4*)&xr[KF + k];
                *(float2*)&T[(size_t)(k + 0) * 132 + 2 * m] = make_float2(c4.x, s4.x);
                *(float2*)&T[(size_t)(k + 1) * 132 + 2 * m] = make_float2(c4.y, s4.y);
                *(float2*)&T[(size_t)(k + 2) * 132 + 2 * m] = make_float2(c4.z, s4.z);
                *(float2*)&T[(size_t)(k + 3) * 132 + 2 * m] = make_float2(c4.w, s4.w);
            }
            if (tid < 64) sqm[tid] = g_sq[m0 + tid];
        }
        __syncthreads();

        // compute: warp w handles n_local = w*8 + i; lane handles m = m0+2ln, +1
        for (int i = 0; i < 8; i++) {
            int nl = w * 8 + i;
            const float2* cvp = &scv[nl * 32];
            const unsigned char* ixp = &sidx[nl * 32];
            float aC0 = 0.f, aS0 = 0.f, aC1 = 0.f, aS1 = 0.f;
#pragma unroll
            for (int j = 0; j < 32; j++) {
                int k = ixp[j];
                float2 cs = cvp[j];
                float4 t = *(const float4*)&T[(size_t)k * 132 + ln * 4];
                aC0 = __fmaf_rn(cs.x, t.x, aC0);
                aS0 = __fmaf_rn(cs.y, t.y, aS0);
                aC1 = __fmaf_rn(cs.x, t.z, aC1);
                aS1 = __fmaf_rn(cs.y, t.w, aS1);
            }
            float sr = sqn[nl];
            float nv0 = __fadd_rn(aC0, aS0);
            float nv1 = __fadd_rn(aC1, aS1);
            float d0 = __fsqrt_rn(__fadd_rn(__fmul_rn(sr, sqm[2 * ln]), EPSF));
            float d1 = __fsqrt_rn(__fadd_rn(__fmul_rn(sr, sqm[2 * ln + 1]), EPSF));
            float v0 = __fdiv_rn(nv0, d0);
            float v1 = __fdiv_rn(nv1, d1);
            *(float2*)&out[(size_t)(n0 + nl) * NN + m0 + 2 * ln] = make_float2(v0, v1);
            if (bi != bj) {
                vT[(size_t)(2 * ln) * 132 + nl]     = v0;
                vT[(size_t)(2 * ln + 1) * 132 + nl] = v1;
            }
        }
        __syncthreads();

        if (bi != bj) {
            // coalesced mirror flush: out[m0+m][n0 .. n0+128)
            for (int i = tid; i < 2048; i += 512) {
                int m = i >> 5;       // 0..63
                int nq = i & 31;      // float4 index within 128 floats
                float4 v = *(const float4*)&vT[(size_t)m * 132 + nq * 4];
                *(float4*)&out[(size_t)(m0 + m) * NN + n0 + nq * 4] = v;
            }
        }
    }
}

// =====================================================================
// Stage C (fused): rowsum in fp32 (XLA:GPU reduction order) + positive
// stats of R' = R/d from register-held values.
// =====================================================================
__global__ void __launch_bounds__(1024) rowsum_kernel(const float* __restrict__ R) {
    int row = blockIdx.x;
    const float* r = R + (size_t)row * NN;
    int t = threadIdx.x;

    float vals[8];
    float a0 = 0.f, a1 = 0.f;
#pragma unroll
    for (int j = 0; j < 4; j++) {
        int i = t * 2 + j * 2048;
        vals[j * 2]     = r[i];
        vals[j * 2 + 1] = r[i + 1];
        a0 = __fadd_rn(a0, vals[j * 2]);
        a1 = __fadd_rn(a1, vals[j * 2 + 1]);
    }
    float acc = __fadd_rn(a0, a1);
#pragma unroll
    for (int o = 16; o > 0; o >>= 1)
        acc = __fadd_rn(acc, __shfl_down_sync(0xffffffffu, acc, o));
    __shared__ float wsh[32];
    __shared__ float sd;
    if ((t & 31) == 0) wsh[t >> 5] = acc;
    __syncthreads();
    if (t < 32) {
        float vv = wsh[t];
#pragma unroll
        for (int o = 16; o > 0; o >>= 1)
            vv = __fadd_rn(vv, __shfl_down_sync(0xffffffffu, vv, o));
        if (t == 0) { float d = __fadd_rn(vv, EPSF); g_d[row] = d; sd = d; }
    }
    __syncthreads();

    float d = sd;
    double ps = 0.0; int pc = 0;
#pragma unroll
    for (int j = 0; j < 8; j++) {
        float rp = __fdiv_rn(vals[j], d);
        if (rp > 0.f) { ps += (double)rp; pc++; }
    }
#pragma unroll
    for (int o = 16; o > 0; o >>= 1) {
        ps += __shfl_down_sync(0xffffffffu, ps, o);
        pc += __shfl_down_sync(0xffffffffu, pc, o);
    }
    __shared__ double wps[32];
    __shared__ int    wpc[32];
    if ((t & 31) == 0) { wps[t >> 5] = ps; wpc[t >> 5] = pc; }
    __syncthreads();
    if (t < 32) {
        double p2 = wps[t]; int c2 = wpc[t];
#pragma unroll
        for (int o = 16; o > 0; o >>= 1) {
            p2 += __shfl_down_sync(0xffffffffu, p2, o);
            c2 += __shfl_down_sync(0xffffffffu, c2, o);
        }
        if (t == 0) { g_rowPS[row] = p2; g_rowPC[row] = c2; }
    }
}

// =====================================================================
// Stage D: tau = mean of strictly-positive R'
// =====================================================================
__global__ void __launch_bounds__(1024) tau_kernel() {
    __shared__ double sps[1024]; __shared__ long long spc[1024];
    double ps = 0.0; long long pc = 0;
    for (int rw = threadIdx.x; rw < NN; rw += 1024) { ps += g_rowPS[rw]; pc += g_rowPC[rw]; }
    sps[threadIdx.x] = ps; spc[threadIdx.x] = pc;
    __syncthreads();
    for (int o = 512; o > 0; o >>= 1) {
        if (threadIdx.x < o) {
            sps[threadIdx.x] += sps[threadIdx.x + o];
            spc[threadIdx.x] += spc[threadIdx.x + o];
        }
        __syncthreads();
    }
    if (threadIdx.x == 0) {
        float psf = (float)sps[0];
        float cf  = fmaxf((float)spc[0], 1.0f);
        float mean = __fdiv_rn(psf, cf);
        g_tau = (mean > 0.f) ? mean : 1.0f;
    }
}

// =====================================================================
// Stage E: R_hat = where(R/d >= tau, R/d, 0)   (in-place)
// =====================================================================
__global__ void thresh_kernel(float* __restrict__ out) {
    float tau = g_tau;
    const size_t tot = (size_t)NN * NN / 4;
    for (size_t i = (size_t)blockIdx.x * blockDim.x + threadIdx.x; i < tot;
         i += (size_t)gridDim.x * blockDim.x) {
        int row = (int)(i >> 11);
        float d = g_d[row];
        float4 v = ((const float4*)out)[i];
        v.x = __fdiv_rn(v.x, d); v.y = __fdiv_rn(v.y, d);
        v.z = __fdiv_rn(v.z, d); v.w = __fdiv_rn(v.w, d);
        v.x = (v.x >= tau) ? v.x : 0.f;
        v.y = (v.y >= tau) ? v.y : 0.f;
        v.z = (v.z >= tau) ? v.z : 0.f;
        v.w = (v.w >= tau) ? v.w : 0.f;
        ((float4*)out)[i] = v;
    }
}

// =====================================================================
extern "C" void kernel_launch(void* const* d_in, const int* in_sizes, int n_in,
                              void* d_out, int out_size) {
    const float* P = (const float*)d_in[0];
    const float* A = (const float*)d_in[1];
    float* out = (float*)d_out;

    cudaFuncSetAttribute(sgemm_sparse, cudaFuncAttributeMaxDynamicSharedMemorySize,
                         SM_TOTAL);

    prep_kernel<<<NN / 4, 128>>>(P, A);
    sgemm_sparse<<<dim3(64, 64), 512, SM_TOTAL>>>(out);
    rowsum_kernel<<<NN, 1024>>>(out);
    tau_kernel<<<1, 1024>>>();
    thresh_kernel<<<4096, 256>>>(out);
}